// round 8
// baseline (speedup 1.0000x reference)
#include <cuda_runtime.h>
#include <cuda_bf16.h>

// relu(segment_sum(x @ W^T + b))  ==  relu(segment_sum(x) @ W^T + count * b)
// N=500000, H=256, B=1024, seg_ids sorted ascending.
//
// Pipeline (3 kernels):
//   1. transpose_W:  WT[k][j] = W[j][k]            (~1.5us, 256KB)
//   2. segsum:       pooledT[k][g] += x[r][k]      (HBM roofline, ~74us)
//   3. finish:       register outer-product GEMM from k-major GLOBAL
//                    operands -- no smem tiles at all. Per warp per k:
//                    1 wf (WT, 128B) + 1 wf (pooledT, 32B) + 8 FFMA/thread.
//                    FFMA-bound at ~4us (previous smem versions were
//                    L1-wavefront-bound at ~19us).
// Scratch starts zeroed (CUDA zero-inits __device__ globals); finish
// re-zeros exactly what it consumed via per-seg-tile arrival counters, so
// every graph replay sees zeroed scratch and does identical work.

#define H 256
#define HV 64                  // H/4
#define B 1024
#define TARGET_GRID 1184       // segsum: 148 SMs * 8 blocks ceiling
#define RPI 32                 // segsum rows per iteration
#define JT 8                   // finish: j tiles (32 outputs each)
#define ST 32                  // finish: segment tiles (32 segs each)
#define FIN_THREADS 128

__device__ float g_pooledT[H * B];       // [k][g] k-major pooled (zero-init)
__device__ float g_count[B];             // nodes per segment    (zero-init)
__device__ float g_WT[H * H];            // [k][j] k-major W (rewritten/launch)
__device__ unsigned int g_done[ST];      // per-seg-tile arrival counters

// ---------------------------------------------------------------------------
// Kernel 0: W transpose, 32x32 tiles, classic padded-smem. grid 64, block 256.
// ---------------------------------------------------------------------------
__global__ void __launch_bounds__(256) transpose_W_kernel(const float* __restrict__ W)
{
    __shared__ float ts[32][33];
    const int t  = threadIdx.x;
    const int tx = t & 31;
    const int ty = t >> 5;              // 0..7
    const int bx = blockIdx.x & 7;      // k-tile
    const int by = blockIdx.x >> 3;     // j-tile

    #pragma unroll
    for (int i = 0; i < 4; ++i)
        ts[ty + 8 * i][tx] = __ldg(&W[(size_t)(by * 32 + ty + 8 * i) * H + bx * 32 + tx]);
    __syncthreads();
    #pragma unroll
    for (int i = 0; i < 4; ++i)
        g_WT[(size_t)(bx * 32 + ty + 8 * i) * H + by * 32 + tx] = ts[tx][ty + 8 * i];
}

// ---------------------------------------------------------------------------
// Kernel 1: segment-sum of x into TRANSPOSED pooledT.  (~74us, HBM roofline)
// Loads identical to previous rounds; only the atomic destinations changed.
// ---------------------------------------------------------------------------
__device__ __forceinline__ void flush_acc(float4& acc, int cur, int c) {
    atomicAdd(&g_pooledT[(c * 4 + 0) * B + cur], acc.x);
    atomicAdd(&g_pooledT[(c * 4 + 1) * B + cur], acc.y);
    atomicAdd(&g_pooledT[(c * 4 + 2) * B + cur], acc.z);
    atomicAdd(&g_pooledT[(c * 4 + 3) * B + cur], acc.w);
    acc = make_float4(0.f, 0.f, 0.f, 0.f);
}

__global__ void __launch_bounds__(H) segsum_kernel(
    const float* __restrict__ x, const int* __restrict__ seg,
    int N, int rows_per_block)
{
    int r0 = blockIdx.x * rows_per_block;
    int r1 = min(r0 + rows_per_block, N);
    if (r0 >= r1) return;

    const int tid    = threadIdx.x;
    const int c      = tid & 63;
    const int rowoff = tid >> 6;
    const float4* __restrict__ x4 = reinterpret_cast<const float4*>(x);

    float4 acc = make_float4(0.f, 0.f, 0.f, 0.f);
    int cur       = __ldg(&seg[r0]);
    int run_start = r0;

    int r = r0;
    for (; r + RPI <= r1; r += RPI) {
        size_t base = (size_t)(r + rowoff) * HV + c;
        float4 v0 = __ldg(&x4[base + 0 * 4 * HV]);
        float4 v1 = __ldg(&x4[base + 1 * 4 * HV]);
        float4 v2 = __ldg(&x4[base + 2 * 4 * HV]);
        float4 v3 = __ldg(&x4[base + 3 * 4 * HV]);
        float4 v4 = __ldg(&x4[base + 4 * 4 * HV]);
        float4 v5 = __ldg(&x4[base + 5 * 4 * HV]);
        float4 v6 = __ldg(&x4[base + 6 * 4 * HV]);
        float4 v7 = __ldg(&x4[base + 7 * 4 * HV]);
        int s_last = __ldg(&seg[r + RPI - 1]);

        if (s_last == cur) {
            acc.x += ((v0.x + v1.x) + (v2.x + v3.x)) + ((v4.x + v5.x) + (v6.x + v7.x));
            acc.y += ((v0.y + v1.y) + (v2.y + v3.y)) + ((v4.y + v5.y) + (v6.y + v7.y));
            acc.z += ((v0.z + v1.z) + (v2.z + v3.z)) + ((v4.z + v5.z) + (v6.z + v7.z));
            acc.w += ((v0.w + v1.w) + (v2.w + v3.w)) + ((v4.w + v5.w) + (v6.w + v7.w));
        } else {
            float4 vv[8] = {v0, v1, v2, v3, v4, v5, v6, v7};
            #pragma unroll
            for (int k = 0; k < RPI; ++k) {
                int rr = r + k;
                int s = __ldg(&seg[rr]);
                if (s != cur) {
                    flush_acc(acc, cur, c);
                    if (tid == 0)
                        atomicAdd(&g_count[cur], (float)(rr - run_start));
                    cur = s; run_start = rr;
                }
                if ((k & 3) == rowoff) {
                    float4 v = vv[k >> 2];
                    acc.x += v.x; acc.y += v.y; acc.z += v.z; acc.w += v.w;
                }
            }
        }
    }
    for (; r < r1; ++r) {
        int s = __ldg(&seg[r]);
        if (s != cur) {
            flush_acc(acc, cur, c);
            if (tid == 0) atomicAdd(&g_count[cur], (float)(r - run_start));
            cur = s; run_start = r;
        }
        if (rowoff == 0) {
            float4 v = __ldg(&x4[(size_t)r * HV + c]);
            acc.x += v.x; acc.y += v.y; acc.z += v.z; acc.w += v.w;
        }
    }
    flush_acc(acc, cur, c);
    if (tid == 0) atomicAdd(&g_count[cur], (float)(r1 - run_start));
}

// ---------------------------------------------------------------------------
// Kernel 2: register outer-product epilogue. grid 256 = 8 jt x 32 st,
// block 128 threads, tile 32j x 32s, thread = 2j x 4s.
//   j2 = t&15 -> j = j0 + j2*2 + {0,1};  s4 = t>>4 -> s = s4*4 + {0..3}
// Per k: w = WT[k][j pair] (LDG.64, warp = 128B contiguous, 1 wf)
//        p = pooledT[k][s quad] (LDG.128, warp = 2x16B, 1 wf)
//        8 FFMA into registers. No shared-memory tiles.
// ---------------------------------------------------------------------------
__global__ void __launch_bounds__(FIN_THREADS) finish_kernel(
    const float* __restrict__ bias, float* __restrict__ out)
{
    const int jt = blockIdx.x & (JT - 1);
    const int st = blockIdx.x >> 3;
    const int j0 = jt * 32;
    const int g0 = st * 32;
    const int t  = threadIdx.x;
    const int j2 = t & 15;              // float2 column within j tile
    const int s4 = t >> 4;              // 0..7: float4 group within seg tile

    __shared__ int s_last_flag;

    const float2* __restrict__ wt2 =
        reinterpret_cast<const float2*>(g_WT) + (j0 >> 1) + j2;   // +k*128
    const float4* __restrict__ pt4 =
        reinterpret_cast<const float4*>(g_pooledT) + (g0 >> 2) + s4; // +k*256

    const float2 bj = *reinterpret_cast<const float2*>(&bias[j0 + j2 * 2]);
    float a0x, a0y, a0z, a0w, a1x, a1y, a1z, a1w;
    {
        float c0 = g_count[g0 + s4 * 4 + 0];
        float c1 = g_count[g0 + s4 * 4 + 1];
        float c2 = g_count[g0 + s4 * 4 + 2];
        float c3 = g_count[g0 + s4 * 4 + 3];
        a0x = c0 * bj.x; a0y = c1 * bj.x; a0z = c2 * bj.x; a0w = c3 * bj.x;
        a1x = c0 * bj.y; a1y = c1 * bj.y; a1z = c2 * bj.y; a1w = c3 * bj.y;
    }

    #pragma unroll 8
    for (int k = 0; k < H; ++k) {
        float2 w = __ldg(&wt2[k * (H / 2)]);
        float4 p = __ldg(&pt4[k * (B / 4)]);
        a0x += w.x * p.x; a0y += w.x * p.y; a0z += w.x * p.z; a0w += w.x * p.w;
        a1x += w.y * p.x; a1y += w.y * p.y; a1z += w.y * p.z; a1w += w.y * p.w;
    }

    {
        float2* o2 = reinterpret_cast<float2*>(out);
        const int jo = (j0 + j2 * 2) >> 1;
        int g = g0 + s4 * 4;
        o2[(size_t)(g + 0) * (H / 2) + jo] = make_float2(fmaxf(a0x, 0.f), fmaxf(a1x, 0.f));
        o2[(size_t)(g + 1) * (H / 2) + jo] = make_float2(fmaxf(a0y, 0.f), fmaxf(a1y, 0.f));
        o2[(size_t)(g + 2) * (H / 2) + jo] = make_float2(fmaxf(a0z, 0.f), fmaxf(a1z, 0.f));
        o2[(size_t)(g + 3) * (H / 2) + jo] = make_float2(fmaxf(a0w, 0.f), fmaxf(a1w, 0.f));
    }

    // ---- last j-tile block for this seg-tile re-zeros its scratch region
    __syncthreads();            // all pooledT reads complete (consumed)
    if (t == 0) {
        __threadfence();
        s_last_flag = (atomicAdd(&g_done[st], 1u) == JT - 1) ? 1 : 0;
    }
    __syncthreads();
    if (s_last_flag) {
        float4* pw = reinterpret_cast<float4*>(g_pooledT) + (g0 >> 2);
        const float4 z = make_float4(0.f, 0.f, 0.f, 0.f);
        for (int idx = t; idx < H * 8; idx += FIN_THREADS) {
            int k = idx >> 3, c = idx & 7;
            pw[(size_t)k * (B / 4) + c] = z;
        }
        if (t < 32) g_count[g0 + t] = 0.f;
        if (t == 0) g_done[st] = 0u;
    }
}

// ---------------------------------------------------------------------------
// Launch
// ---------------------------------------------------------------------------
extern "C" void kernel_launch(void* const* d_in, const int* in_sizes, int n_in,
                              void* d_out, int out_size)
{
    const float* x   = (const float*)d_in[0];   // [N, 256]
    const int*   seg = (const int*)  d_in[1];   // [N]
    const float* W   = (const float*)d_in[2];   // [256, 256]
    const float* b   = (const float*)d_in[3];   // [256]
    float* out = (float*)d_out;                 // [1024, 256]

    const int N = in_sizes[0] / H;

    int rpb = (N + TARGET_GRID - 1) / TARGET_GRID;
    rpb = ((rpb + RPI - 1) / RPI) * RPI;        // N=500000 -> 448
    int grid = (N + rpb - 1) / rpb;             // -> 1117 (single wave)

    transpose_W_kernel<<<64, 256>>>(W);
    segsum_kernel<<<grid, H>>>(x, seg, N, rpb);
    finish_kernel<<<JT * ST, FIN_THREADS>>>(b, out);
}

// round 9
// speedup vs baseline: 2.1267x; 2.1267x over previous
#include <cuda_runtime.h>
#include <cuda_bf16.h>

// relu(segment_sum(x @ W^T + b))  ==  relu(segment_sum(x) @ W^T + count * b)
// N=500000, H=256, B=1024, seg_ids sorted ascending.
//
// Kernel 1 (segsum): row-major pooled, proven ~74us = HBM roofline. DO NOT TOUCH.
// Kernel 2 (finish): reduction-layout GEMM. One warp = 4j x 4s output tile,
//   lanes span k. Both operands read k-contiguous from their NATIVE row-major
//   layouts (LDG.128, 4 wavefronts per warp-instr) -- no transposes, no smem
//   tiles (every smem/transpose variant measured ~19us, L1-wavefront-bound).
//   Butterfly-shfl reduction, lane<4 stores float4 outputs.
// Scratch starts zeroed (CUDA zero-inits __device__ globals); finish re-zeros
// exactly the region it consumed via per-s-quad arrival counters, so every
// graph replay sees zeroed scratch and does identical work.

#define H 256
#define HV 64                  // H/4
#define B 1024
#define TARGET_GRID 1184       // segsum: 148 SMs * 8 blocks ceiling
#define RPI 32                 // segsum rows per iteration
#define SQ (B / 4)             // 256 s-quads (finish re-zero granularity)

__device__ float g_pooled[B * H];        // segment sums of x (zero-init)
__device__ float g_count[B];             // nodes per segment  (zero-init)
__device__ unsigned int g_done[SQ];      // per-s-quad arrival counters

// ---------------------------------------------------------------------------
// Kernel 1: segment-sum of x (row-major pooled).  ~74us, at HBM roofline.
// ---------------------------------------------------------------------------
__device__ __forceinline__ void flush_acc(float4& acc, int cur, int c) {
    float* dst = &g_pooled[cur * H + c * 4];
    atomicAdd(dst + 0, acc.x);
    atomicAdd(dst + 1, acc.y);
    atomicAdd(dst + 2, acc.z);
    atomicAdd(dst + 3, acc.w);
    acc = make_float4(0.f, 0.f, 0.f, 0.f);
}

__global__ void __launch_bounds__(H) segsum_kernel(
    const float* __restrict__ x, const int* __restrict__ seg,
    int N, int rows_per_block)
{
    int r0 = blockIdx.x * rows_per_block;
    int r1 = min(r0 + rows_per_block, N);
    if (r0 >= r1) return;

    const int tid    = threadIdx.x;
    const int c      = tid & 63;
    const int rowoff = tid >> 6;
    const float4* __restrict__ x4 = reinterpret_cast<const float4*>(x);

    float4 acc = make_float4(0.f, 0.f, 0.f, 0.f);
    int cur       = __ldg(&seg[r0]);
    int run_start = r0;

    int r = r0;
    for (; r + RPI <= r1; r += RPI) {
        size_t base = (size_t)(r + rowoff) * HV + c;
        float4 v0 = __ldg(&x4[base + 0 * 4 * HV]);
        float4 v1 = __ldg(&x4[base + 1 * 4 * HV]);
        float4 v2 = __ldg(&x4[base + 2 * 4 * HV]);
        float4 v3 = __ldg(&x4[base + 3 * 4 * HV]);
        float4 v4 = __ldg(&x4[base + 4 * 4 * HV]);
        float4 v5 = __ldg(&x4[base + 5 * 4 * HV]);
        float4 v6 = __ldg(&x4[base + 6 * 4 * HV]);
        float4 v7 = __ldg(&x4[base + 7 * 4 * HV]);
        int s_last = __ldg(&seg[r + RPI - 1]);

        if (s_last == cur) {
            acc.x += ((v0.x + v1.x) + (v2.x + v3.x)) + ((v4.x + v5.x) + (v6.x + v7.x));
            acc.y += ((v0.y + v1.y) + (v2.y + v3.y)) + ((v4.y + v5.y) + (v6.y + v7.y));
            acc.z += ((v0.z + v1.z) + (v2.z + v3.z)) + ((v4.z + v5.z) + (v6.z + v7.z));
            acc.w += ((v0.w + v1.w) + (v2.w + v3.w)) + ((v4.w + v5.w) + (v6.w + v7.w));
        } else {
            float4 vv[8] = {v0, v1, v2, v3, v4, v5, v6, v7};
            #pragma unroll
            for (int k = 0; k < RPI; ++k) {
                int rr = r + k;
                int s = __ldg(&seg[rr]);
                if (s != cur) {
                    flush_acc(acc, cur, c);
                    if (tid == 0)
                        atomicAdd(&g_count[cur], (float)(rr - run_start));
                    cur = s; run_start = rr;
                }
                if ((k & 3) == rowoff) {
                    float4 v = vv[k >> 2];
                    acc.x += v.x; acc.y += v.y; acc.z += v.z; acc.w += v.w;
                }
            }
        }
    }
    for (; r < r1; ++r) {
        int s = __ldg(&seg[r]);
        if (s != cur) {
            flush_acc(acc, cur, c);
            if (tid == 0) atomicAdd(&g_count[cur], (float)(r - run_start));
            cur = s; run_start = r;
        }
        if (rowoff == 0) {
            float4 v = __ldg(&x4[(size_t)r * HV + c]);
            acc.x += v.x; acc.y += v.y; acc.z += v.z; acc.w += v.w;
        }
    }
    flush_acc(acc, cur, c);
    if (tid == 0) atomicAdd(&g_count[cur], (float)(r1 - run_start));
}

// ---------------------------------------------------------------------------
// Kernel 2: reduction-layout epilogue GEMM. grid 2048, block 256 (8 warps).
// Warp wg: j0 = (wg & 63)*4, s0 = (wg >> 6)*4.  Lane owns k-strips
// k4 = i*32 + lane (i=0,1). Per warp: 8 LDG.128 (W rows) + 8 LDG.128
// (pooled rows) -- both lane-contiguous 512B -- 128 FFMA, butterfly reduce.
// All 8 warps of a block share s0's block... (share the same s-quad), so
// pooled lines are L1-resident. Blocks b = q*8..q*8+7 share s-quad q; the
// last one to arrive re-zeros that scratch region.
// ---------------------------------------------------------------------------
__global__ void __launch_bounds__(256) finish_kernel(
    const float* __restrict__ W, const float* __restrict__ bias,
    float* __restrict__ out)
{
    const int t    = threadIdx.x;
    const int warp = t >> 5;
    const int lane = t & 31;
    const int wg   = blockIdx.x * 8 + warp;
    const int j0   = (wg & 63) * 4;
    const int s0   = (wg >> 6) * 4;

    const float4* __restrict__ W4 = reinterpret_cast<const float4*>(W);
    const float4* __restrict__ P4 = reinterpret_cast<const float4*>(g_pooled);

    float acc[4][4];                    // [jj][ss] partial dots
    #pragma unroll
    for (int a = 0; a < 4; ++a)
        #pragma unroll
        for (int b2 = 0; b2 < 4; ++b2) acc[a][b2] = 0.f;

    #pragma unroll
    for (int i = 0; i < 2; ++i) {
        const int k4 = i * 32 + lane;
        float4 wv0 = __ldg(&W4[(size_t)(j0 + 0) * HV + k4]);
        float4 wv1 = __ldg(&W4[(size_t)(j0 + 1) * HV + k4]);
        float4 wv2 = __ldg(&W4[(size_t)(j0 + 2) * HV + k4]);
        float4 wv3 = __ldg(&W4[(size_t)(j0 + 3) * HV + k4]);
        float4 pv0 = P4[(size_t)(s0 + 0) * HV + k4];
        float4 pv1 = P4[(size_t)(s0 + 1) * HV + k4];
        float4 pv2 = P4[(size_t)(s0 + 2) * HV + k4];
        float4 pv3 = P4[(size_t)(s0 + 3) * HV + k4];

        #pragma unroll
        for (int jj = 0; jj < 4; ++jj) {
            float4 w = (jj == 0) ? wv0 : (jj == 1) ? wv1 : (jj == 2) ? wv2 : wv3;
            acc[jj][0] += w.x * pv0.x + w.y * pv0.y + w.z * pv0.z + w.w * pv0.w;
            acc[jj][1] += w.x * pv1.x + w.y * pv1.y + w.z * pv1.z + w.w * pv1.w;
            acc[jj][2] += w.x * pv2.x + w.y * pv2.y + w.z * pv2.z + w.w * pv2.w;
            acc[jj][3] += w.x * pv3.x + w.y * pv3.y + w.z * pv3.z + w.w * pv3.w;
        }
    }

    // butterfly reduce the 16 partials across 32 lanes
    #pragma unroll
    for (int d = 16; d >= 1; d >>= 1) {
        #pragma unroll
        for (int jj = 0; jj < 4; ++jj) {
            #pragma unroll
            for (int ss = 0; ss < 4; ++ss)
                acc[jj][ss] += __shfl_xor_sync(0xffffffffu, acc[jj][ss], d);
        }
    }

    if (lane < 4) {
        const int g   = s0 + lane;
        const float cnt = g_count[g];
        const float4 b4 = __ldg(reinterpret_cast<const float4*>(bias) + (j0 >> 2));
        float4 o;
        o.x = fmaxf(acc[0][lane] + cnt * b4.x, 0.f);
        o.y = fmaxf(acc[1][lane] + cnt * b4.y, 0.f);
        o.z = fmaxf(acc[2][lane] + cnt * b4.z, 0.f);
        o.w = fmaxf(acc[3][lane] + cnt * b4.w, 0.f);
        reinterpret_cast<float4*>(out)[(size_t)g * HV + (j0 >> 2)] = o;
    }

    // ---- last of the 8 sibling blocks for s-quad q re-zeros its scratch ----
    __shared__ int s_last;
    __syncthreads();                    // all pooled reads in block complete
    if (t == 0) {
        __threadfence();
        s_last = (atomicAdd(&g_done[blockIdx.x >> 3], 1u) == 7u) ? 1 : 0;
    }
    __syncthreads();
    if (s_last) {
        const int q0 = (blockIdx.x >> 3) * 4;          // first segment of quad
        float4* pz = reinterpret_cast<float4*>(g_pooled) + (size_t)q0 * HV;
        pz[t] = make_float4(0.f, 0.f, 0.f, 0.f);       // 4 segs * 64 = 256 = blockDim
        if (t < 4) g_count[q0 + t] = 0.f;
        if (t == 0) g_done[blockIdx.x >> 3] = 0u;
    }
}

// ---------------------------------------------------------------------------
// Launch
// ---------------------------------------------------------------------------
extern "C" void kernel_launch(void* const* d_in, const int* in_sizes, int n_in,
                              void* d_out, int out_size)
{
    const float* x   = (const float*)d_in[0];   // [N, 256]
    const int*   seg = (const int*)  d_in[1];   // [N]
    const float* W   = (const float*)d_in[2];   // [256, 256]
    const float* b   = (const float*)d_in[3];   // [256]
    float* out = (float*)d_out;                 // [1024, 256]

    const int N = in_sizes[0] / H;

    int rpb = (N + TARGET_GRID - 1) / TARGET_GRID;
    rpb = ((rpb + RPI - 1) / RPI) * RPI;        // N=500000 -> 448
    int grid = (N + rpb - 1) / rpb;             // -> 1117 (single wave)

    segsum_kernel<<<grid, H>>>(x, seg, N, rpb);
    finish_kernel<<<2048, 256>>>(W, b, out);
}